// round 5
// baseline (speedup 1.0000x reference)
#include <cuda_runtime.h>
#include <cuda_fp16.h>

// Problem constants (fixed by the dataset)
#define NN 50000
#define LL 4
#define EE 1600000
#define CC 128
#define NM 8          // m<4 -> phi_inverse[l], m>=4 -> phi[l-4]

#define GEMM_R 16
#define GEMM_BLOCKS ((LL * NN) / GEMM_R)      // 12500
#define HIST_BPM (EE / 512)                   // 3125 blocks per matrix (4 edges/thread, 128 thr)
#define HIST_BLOCKS (NM * HIST_BPM)           // 25000

// ----------------------------------------------------------------------------
// Scratch (static device globals; allocation-free per harness rules)
// ----------------------------------------------------------------------------
__device__ int   g_rowptr[NM][NN + 1];
__device__ int   g_cnt[NM][NN];
__device__ int2  g_edge[(size_t)NM * EE];                    // {col, val bits}
__device__ __align__(16) __half g_Y1[(size_t)LL * NN * CC];  // feats @ W (fp16)
__device__ __align__(16) __half g_Y2[(size_t)LL * NN * CC];  // theta*(phi_inv@Y1) (fp16)

// packed dual fp32 FMA: d.lo += a.lo*b.lo ; d.hi += a.hi*b.hi
__device__ __forceinline__ void ffma2(unsigned long long& d,
                                      unsigned long long a,
                                      unsigned long long b) {
    asm("fma.rn.f32x2 %0, %1, %2, %0;" : "+l"(d) : "l"(a), "l"(b));
}

// ----------------------------------------------------------------------------
// 1) zero the per-row counters
// ----------------------------------------------------------------------------
__global__ void zero_cnt_kernel() {
    int i = blockIdx.x * blockDim.x + threadIdx.x;
    if (i < NM * NN) ((int*)g_cnt)[i] = 0;
}

// ----------------------------------------------------------------------------
// 2) fused GEMM (Y1 = feats @ W, fp16 out) + row histogram
//    blocks [0, GEMM_BLOCKS): gemm; rest: histogram (4 edges/thread, int4 loads)
// ----------------------------------------------------------------------------
__global__ void __launch_bounds__(128) gemm_hist_kernel(
    const float* __restrict__ feats, const float* __restrict__ W,
    const int* __restrict__ phi_idx, const int* __restrict__ inv_idx) {
    int tid = threadIdx.x;

    if (blockIdx.x >= GEMM_BLOCKS) {
        // ---- histogram part ----
        int bid = blockIdx.x - GEMM_BLOCKS;
        int m   = bid / HIST_BPM;
        int blk = bid - m * HIST_BPM;
        const int* rows = (m < LL) ? (inv_idx + (size_t)m * 2 * EE)
                                   : (phi_idx + (size_t)(m - LL) * 2 * EE);
        int e = blk * 512 + tid * 4;
        int4 r4 = *(const int4*)(rows + e);
        atomicAdd(&g_cnt[m][r4.x], 1);
        atomicAdd(&g_cnt[m][r4.y], 1);
        atomicAdd(&g_cnt[m][r4.z], 1);
        atomicAdd(&g_cnt[m][r4.w], 1);
        return;
    }

    // ---- GEMM part: 16 rows per block, thread tid = output column ----
    __shared__ __align__(16) float Ws[CC * 66];      // W half, transposed [c][k], pad 66
    __shared__ __align__(16) float Fs[GEMM_R * CC];  // feature tile [rr][k]

    int row0 = blockIdx.x * GEMM_R;  // t = l*NN + n

    #pragma unroll
    for (int rr = 0; rr < GEMM_R; rr++) {
        int t = row0 + rr;
        int l = t / NN;
        int n = t - l * NN;
        Fs[rr * CC + tid] = feats[((size_t)n * LL + l) * CC + tid];
    }

    unsigned long long acc[GEMM_R];
    #pragma unroll
    for (int rr = 0; rr < GEMM_R; rr++) acc[rr] = 0ull;

    for (int h = 0; h < 2; h++) {
        __syncthreads();
        // stage W rows [h*64, h*64+64) transposed: Ws[c*66 + k] = W[(h*64+k)*128 + c]
        #pragma unroll
        for (int i = tid; i < 64 * CC; i += 128) {
            int k = i >> 7;           // 0..63
            int c = i & 127;
            Ws[c * 66 + k] = W[(size_t)(h * 64 + k) * CC + c];
        }
        __syncthreads();

        #pragma unroll
        for (int k = 0; k < 64; k += 4) {
            unsigned long long w01 = *(const unsigned long long*)&Ws[tid * 66 + k];
            unsigned long long w23 = *(const unsigned long long*)&Ws[tid * 66 + k + 2];
            #pragma unroll
            for (int rr = 0; rr < GEMM_R; rr++) {
                ulonglong2 f = *(const ulonglong2*)&Fs[rr * CC + h * 64 + k];
                ffma2(acc[rr], f.x, w01);
                ffma2(acc[rr], f.y, w23);
            }
        }
    }

    #pragma unroll
    for (int rr = 0; rr < GEMM_R; rr++) {
        float lo, hi;
        asm("mov.b64 {%0,%1}, %2;" : "=f"(lo), "=f"(hi) : "l"(acc[rr]));
        float s = lo + hi;
        int t = row0 + rr;
        int l = t / NN;
        int n = t - l * NN;
        g_Y1[(size_t)l * NN * CC + (size_t)n * CC + tid] = __float2half_rn(s);
    }
}

// ----------------------------------------------------------------------------
// 3) exclusive scan per matrix -> rowptr; resets cnt; warp-shuffle scan
// ----------------------------------------------------------------------------
__global__ void scan_kernel() {
    __shared__ int warpsums[32];
    __shared__ int s_carry;
    int m = blockIdx.x;
    int tid = threadIdx.x;
    int lane = tid & 31;
    int w = tid >> 5;
    if (tid == 0) { s_carry = 0; g_rowptr[m][0] = 0; }
    __syncthreads();
    for (int base = 0; base < NN; base += 1024) {
        int i = base + tid;
        int v = (i < NN) ? g_cnt[m][i] : 0;
        int x = v;
        #pragma unroll
        for (int off = 1; off < 32; off <<= 1) {
            int y = __shfl_up_sync(0xffffffffu, x, off);
            if (lane >= off) x += y;
        }
        if (lane == 31) warpsums[w] = x;
        __syncthreads();
        if (w == 0) {
            int s = warpsums[lane];
            #pragma unroll
            for (int off = 1; off < 32; off <<= 1) {
                int y = __shfl_up_sync(0xffffffffu, s, off);
                if (lane >= off) s += y;
            }
            warpsums[lane] = s;
        }
        __syncthreads();
        int incl = x + ((w > 0) ? warpsums[w - 1] : 0);
        if (i < NN) {
            g_rowptr[m][i + 1] = s_carry + incl;
            g_cnt[m][i] = 0;
        }
        __syncthreads();
        if (tid == 1023) s_carry += incl;
        __syncthreads();
    }
}

// ----------------------------------------------------------------------------
// 4) scatter edges into row-sorted records (single 8B store per edge)
// ----------------------------------------------------------------------------
__global__ void scatter_kernel(const int* __restrict__ phi_idx,
                               const float* __restrict__ phi_val,
                               const int* __restrict__ inv_idx,
                               const float* __restrict__ inv_val) {
    int e = blockIdx.x * blockDim.x + threadIdx.x;
    int m = blockIdx.y;
    const int*   base = (m < LL) ? (inv_idx + (size_t)m * 2 * EE)
                                 : (phi_idx + (size_t)(m - LL) * 2 * EE);
    const float* vals = (m < LL) ? (inv_val + (size_t)m * EE)
                                 : (phi_val + (size_t)(m - LL) * EE);
    int   r = base[e];
    int   c = base[EE + e];
    float v = vals[e];
    int pos = g_rowptr[m][r] + atomicAdd(&g_cnt[m][r], 1);
    g_edge[(size_t)m * EE + pos] = make_int2(c, __float_as_int(v));
}

// ----------------------------------------------------------------------------
// 5) SpMM stage 1: Y2[l] = theta .* (phi_inv[l] @ Y1[l])   (fp16 gather, fp32 acc)
//    warp per row; lane owns 4 channels (8B = uint2 of half2)
// ----------------------------------------------------------------------------
__global__ void __launch_bounds__(256) spmm_inv_kernel(const float* __restrict__ theta) {
    int wg   = (blockIdx.x * blockDim.x + threadIdx.x) >> 5;
    int lane = threadIdx.x & 31;
    int l = wg / NN;
    int r = wg - l * NN;
    int start = g_rowptr[l][r];
    int end   = g_rowptr[l][r + 1];
    const uint2* Xv = (const uint2*)(g_Y1 + (size_t)l * NN * CC);
    const int2*  ge = g_edge + (size_t)l * EE;

    float4 acc = make_float4(0.f, 0.f, 0.f, 0.f);
    for (int e0 = start; e0 < end; e0 += 32) {
        int me = e0 + lane;
        int2 rec = (me < end) ? ge[me] : make_int2(0, 0);
        int cnt = min(32, end - e0);
        #pragma unroll 4
        for (int j = 0; j < cnt; j++) {
            int   col = __shfl_sync(0xffffffffu, rec.x, j);
            float val = __int_as_float(__shfl_sync(0xffffffffu, rec.y, j));
            uint2 xw = Xv[col * 32 + lane];
            float2 fa = __half22float2(*(const half2*)&xw.x);
            float2 fb = __half22float2(*(const half2*)&xw.y);
            acc.x = fmaf(val, fa.x, acc.x);
            acc.y = fmaf(val, fa.y, acc.y);
            acc.z = fmaf(val, fb.x, acc.z);
            acc.w = fmaf(val, fb.y, acc.w);
        }
    }
    float t = theta[r];
    half2 h0 = __floats2half2_rn(acc.x * t, acc.y * t);
    half2 h1 = __floats2half2_rn(acc.z * t, acc.w * t);
    uint2* out = (uint2*)(g_Y2 + (size_t)l * NN * CC);
    uint2 o;
    o.x = *(const unsigned int*)&h0;
    o.y = *(const unsigned int*)&h1;
    out[r * 32 + lane] = o;
}

// ----------------------------------------------------------------------------
// 6) SpMM stage 2: out[n][l][:] = phi[l] @ Y2[l]   (fp32 output)
// ----------------------------------------------------------------------------
__global__ void __launch_bounds__(256) spmm_phi_kernel(float* __restrict__ outp) {
    int wg   = (blockIdx.x * blockDim.x + threadIdx.x) >> 5;
    int lane = threadIdx.x & 31;
    int l = wg / NN;
    int r = wg - l * NN;
    int m = LL + l;
    int start = g_rowptr[m][r];
    int end   = g_rowptr[m][r + 1];
    const uint2* Xv = (const uint2*)(g_Y2 + (size_t)l * NN * CC);
    const int2*  ge = g_edge + (size_t)m * EE;

    float4 acc = make_float4(0.f, 0.f, 0.f, 0.f);
    for (int e0 = start; e0 < end; e0 += 32) {
        int me = e0 + lane;
        int2 rec = (me < end) ? ge[me] : make_int2(0, 0);
        int cnt = min(32, end - e0);
        #pragma unroll 4
        for (int j = 0; j < cnt; j++) {
            int   col = __shfl_sync(0xffffffffu, rec.x, j);
            float val = __int_as_float(__shfl_sync(0xffffffffu, rec.y, j));
            uint2 xw = Xv[col * 32 + lane];
            float2 fa = __half22float2(*(const half2*)&xw.x);
            float2 fb = __half22float2(*(const half2*)&xw.y);
            acc.x = fmaf(val, fa.x, acc.x);
            acc.y = fmaf(val, fa.y, acc.y);
            acc.z = fmaf(val, fb.x, acc.z);
            acc.w = fmaf(val, fb.y, acc.w);
        }
    }
    float4* out = (float4*)outp;                  // [n][l][c]
    out[(r * LL + l) * 32 + lane] = acc;
}

// ----------------------------------------------------------------------------
// launch
// ----------------------------------------------------------------------------
extern "C" void kernel_launch(void* const* d_in, const int* in_sizes, int n_in,
                              void* d_out, int out_size) {
    const int*   phi_idx = (const int*)d_in[0];    // [L,2,E]
    const float* phi_val = (const float*)d_in[1];  // [L,E]
    const int*   inv_idx = (const int*)d_in[2];    // [L,2,E]
    const float* inv_val = (const float*)d_in[3];  // [L,E]
    const float* feats   = (const float*)d_in[4];  // [N,L,C]
    const float* W       = (const float*)d_in[5];  // [C,C]
    const float* theta   = (const float*)d_in[6];  // [N]
    float*       outp    = (float*)d_out;          // [N,L,C]

    zero_cnt_kernel<<<(NM * NN + 255) / 256, 256>>>();
    gemm_hist_kernel<<<GEMM_BLOCKS + HIST_BLOCKS, 128>>>(feats, W, phi_idx, inv_idx);
    scan_kernel<<<NM, 1024>>>();
    dim3 gE(EE / 256, NM);
    scatter_kernel<<<gE, 256>>>(phi_idx, phi_val, inv_idx, inv_val);
    spmm_inv_kernel<<<(LL * NN) / 8, 256>>>(theta);
    spmm_phi_kernel<<<(LL * NN) / 8, 256>>>(outp);
}

// round 7
// speedup vs baseline: 1.5764x; 1.5764x over previous
#include <cuda_runtime.h>
#include <cuda_fp16.h>

// Problem constants (fixed by the dataset)
#define NN 50000
#define LL 4
#define EE 1600000
#define CC 128
#define NM 8          // m<4 -> phi_inverse[l], m>=4 -> phi[l-4]

#define GEMM_R 16

// ----------------------------------------------------------------------------
// Scratch (static device globals; allocation-free per harness rules)
// ----------------------------------------------------------------------------
__device__ int   g_rowptr[NM][NN + 1];
__device__ int   g_cnt[NM][NN];                              // hist, then cursor=rowptr
__device__ int2  g_edge[(size_t)NM * EE];                    // {col, val bits}
__device__ __align__(16) __half g_Y1[(size_t)LL * NN * CC];  // feats @ W (fp16)
__device__ __align__(16) __half g_Y2[(size_t)LL * NN * CC];  // theta*(phi_inv@Y1) (fp16)

// packed dual fp32 FMA: d.lo += a.lo*b.lo ; d.hi += a.hi*b.hi
__device__ __forceinline__ void ffma2(unsigned long long& d,
                                      unsigned long long a,
                                      unsigned long long b) {
    asm("fma.rn.f32x2 %0, %1, %2, %0;" : "+l"(d) : "l"(a), "l"(b));
}

// ----------------------------------------------------------------------------
// 1) zero the per-row counters
// ----------------------------------------------------------------------------
__global__ void zero_cnt_kernel() {
    int i = blockIdx.x * blockDim.x + threadIdx.x;
    if (i < NM * NN) ((int*)g_cnt)[i] = 0;
}

// ----------------------------------------------------------------------------
// 2) histogram: 4 edges/thread via int4, 128 threads, grid (EE/512, NM)
// ----------------------------------------------------------------------------
__global__ void __launch_bounds__(128) hist_kernel(const int* __restrict__ phi_idx,
                                                   const int* __restrict__ inv_idx) {
    int m = blockIdx.y;
    const int* rows = (m < LL) ? (inv_idx + (size_t)m * 2 * EE)
                               : (phi_idx + (size_t)(m - LL) * 2 * EE);
    int e = blockIdx.x * 512 + threadIdx.x * 4;
    int4 r4 = *(const int4*)(rows + e);
    atomicAdd(&g_cnt[m][r4.x], 1);
    atomicAdd(&g_cnt[m][r4.y], 1);
    atomicAdd(&g_cnt[m][r4.z], 1);
    atomicAdd(&g_cnt[m][r4.w], 1);
}

// ----------------------------------------------------------------------------
// 3) exclusive scan -> rowptr; ALSO writes cnt[i] = row start (scatter cursor)
// ----------------------------------------------------------------------------
__global__ void scan_kernel() {
    __shared__ int warpsums[32];
    __shared__ int s_carry;
    int m = blockIdx.x;
    int tid = threadIdx.x;
    int lane = tid & 31;
    int w = tid >> 5;
    if (tid == 0) { s_carry = 0; g_rowptr[m][0] = 0; }
    __syncthreads();
    for (int base = 0; base < NN; base += 1024) {
        int i = base + tid;
        int v = (i < NN) ? g_cnt[m][i] : 0;
        int x = v;
        #pragma unroll
        for (int off = 1; off < 32; off <<= 1) {
            int y = __shfl_up_sync(0xffffffffu, x, off);
            if (lane >= off) x += y;
        }
        if (lane == 31) warpsums[w] = x;
        __syncthreads();
        if (w == 0) {
            int s = warpsums[lane];
            #pragma unroll
            for (int off = 1; off < 32; off <<= 1) {
                int y = __shfl_up_sync(0xffffffffu, s, off);
                if (lane >= off) s += y;
            }
            warpsums[lane] = s;
        }
        __syncthreads();
        int incl = x + ((w > 0) ? warpsums[w - 1] : 0);
        if (i < NN) {
            g_rowptr[m][i + 1] = s_carry + incl;
            g_cnt[m][i]        = s_carry + incl - v;   // exclusive start = cursor init
        }
        __syncthreads();
        if (tid == 1023) s_carry += incl;
        __syncthreads();
    }
}

// ----------------------------------------------------------------------------
// 4) scatter: cursor atomic gives position directly (no rowptr gather).
//    4 edges/thread via int4/float4; grid (EE/512, NM), 128 threads
// ----------------------------------------------------------------------------
__global__ void __launch_bounds__(128) scatter_kernel(
    const int* __restrict__ phi_idx, const float* __restrict__ phi_val,
    const int* __restrict__ inv_idx, const float* __restrict__ inv_val) {
    int m = blockIdx.y;
    const int*   base = (m < LL) ? (inv_idx + (size_t)m * 2 * EE)
                                 : (phi_idx + (size_t)(m - LL) * 2 * EE);
    const float* vals = (m < LL) ? (inv_val + (size_t)m * EE)
                                 : (phi_val + (size_t)(m - LL) * EE);
    int e = blockIdx.x * 512 + threadIdx.x * 4;
    int4   r4 = *(const int4*)(base + e);
    int4   c4 = *(const int4*)(base + EE + e);
    float4 v4 = *(const float4*)(vals + e);
    int2* eg = g_edge + (size_t)m * EE;
    int p0 = atomicAdd(&g_cnt[m][r4.x], 1);
    eg[p0] = make_int2(c4.x, __float_as_int(v4.x));
    int p1 = atomicAdd(&g_cnt[m][r4.y], 1);
    eg[p1] = make_int2(c4.y, __float_as_int(v4.y));
    int p2 = atomicAdd(&g_cnt[m][r4.z], 1);
    eg[p2] = make_int2(c4.z, __float_as_int(v4.z));
    int p3 = atomicAdd(&g_cnt[m][r4.w], 1);
    eg[p3] = make_int2(c4.w, __float_as_int(v4.w));
}

// ----------------------------------------------------------------------------
// 5) GEMM: Y1 = feats @ W (fp16 out), FFMA2 mainloop, 16 rows/block
// ----------------------------------------------------------------------------
__global__ void __launch_bounds__(128) gemm_kernel(const float* __restrict__ feats,
                                                   const float* __restrict__ W) {
    __shared__ __align__(16) float Ws[CC * 66];      // W half, transposed [c][k], pad 66
    __shared__ __align__(16) float Fs[GEMM_R * CC];  // feature tile [rr][k]
    int tid = threadIdx.x;           // output column c
    int row0 = blockIdx.x * GEMM_R;  // t = l*NN + n

    #pragma unroll
    for (int rr = 0; rr < GEMM_R; rr++) {
        int t = row0 + rr;
        int l = t / NN;
        int n = t - l * NN;
        Fs[rr * CC + tid] = feats[((size_t)n * LL + l) * CC + tid];
    }

    unsigned long long acc[GEMM_R];
    #pragma unroll
    for (int rr = 0; rr < GEMM_R; rr++) acc[rr] = 0ull;

    for (int h = 0; h < 2; h++) {
        __syncthreads();
        #pragma unroll
        for (int i = tid; i < 64 * CC; i += 128) {
            int k = i >> 7;
            int c = i & 127;
            Ws[c * 66 + k] = W[(size_t)(h * 64 + k) * CC + c];
        }
        __syncthreads();

        #pragma unroll
        for (int k = 0; k < 64; k += 4) {
            unsigned long long w01 = *(const unsigned long long*)&Ws[tid * 66 + k];
            unsigned long long w23 = *(const unsigned long long*)&Ws[tid * 66 + k + 2];
            #pragma unroll
            for (int rr = 0; rr < GEMM_R; rr++) {
                ulonglong2 f = *(const ulonglong2*)&Fs[rr * CC + h * 64 + k];
                ffma2(acc[rr], f.x, w01);
                ffma2(acc[rr], f.y, w23);
            }
        }
    }

    #pragma unroll
    for (int rr = 0; rr < GEMM_R; rr++) {
        float lo, hi;
        asm("mov.b64 {%0,%1}, %2;" : "=f"(lo), "=f"(hi) : "l"(acc[rr]));
        float s = lo + hi;
        int t = row0 + rr;
        int l = t / NN;
        int n = t - l * NN;
        g_Y1[(size_t)l * NN * CC + (size_t)n * CC + tid] = __float2half_rn(s);
    }
}

// ----------------------------------------------------------------------------
// 6) SpMM stage 1: Y2[l] = theta .* (phi_inv[l] @ Y1[l])
//    warp/row; edge records read via uniform (broadcast) LDG, no shuffles
// ----------------------------------------------------------------------------
__global__ void __launch_bounds__(256) spmm_inv_kernel(const float* __restrict__ theta) {
    int wg   = (blockIdx.x * blockDim.x + threadIdx.x) >> 5;
    int lane = threadIdx.x & 31;
    int l = wg / NN;
    int r = wg - l * NN;
    int start = __ldg(&g_rowptr[l][r]);
    int end   = __ldg(&g_rowptr[l][r + 1]);
    const uint2* Xv = (const uint2*)(g_Y1 + (size_t)l * NN * CC);
    const int2*  ge = g_edge + (size_t)l * EE;

    float4 acc = make_float4(0.f, 0.f, 0.f, 0.f);
    #pragma unroll 4
    for (int e = start; e < end; e++) {
        int2 rec = __ldg(&ge[e]);                 // uniform across warp -> broadcast
        float val = __int_as_float(rec.y);
        uint2 xw = Xv[(size_t)rec.x * 32 + lane];
        float2 fa = __half22float2(*(const half2*)&xw.x);
        float2 fb = __half22float2(*(const half2*)&xw.y);
        acc.x = fmaf(val, fa.x, acc.x);
        acc.y = fmaf(val, fa.y, acc.y);
        acc.z = fmaf(val, fb.x, acc.z);
        acc.w = fmaf(val, fb.y, acc.w);
    }
    float t = __ldg(&theta[r]);
    half2 h0 = __floats2half2_rn(acc.x * t, acc.y * t);
    half2 h1 = __floats2half2_rn(acc.z * t, acc.w * t);
    uint2 o;
    o.x = *(const unsigned int*)&h0;
    o.y = *(const unsigned int*)&h1;
    ((uint2*)(g_Y2 + (size_t)l * NN * CC))[r * 32 + lane] = o;
}

// ----------------------------------------------------------------------------
// 7) SpMM stage 2: out[n][l][:] = phi[l] @ Y2[l]   (fp32 output)
// ----------------------------------------------------------------------------
__global__ void __launch_bounds__(256) spmm_phi_kernel(float* __restrict__ outp) {
    int wg   = (blockIdx.x * blockDim.x + threadIdx.x) >> 5;
    int lane = threadIdx.x & 31;
    int l = wg / NN;
    int r = wg - l * NN;
    int m = LL + l;
    int start = __ldg(&g_rowptr[m][r]);
    int end   = __ldg(&g_rowptr[m][r + 1]);
    const uint2* Xv = (const uint2*)(g_Y2 + (size_t)l * NN * CC);
    const int2*  ge = g_edge + (size_t)m * EE;

    float4 acc = make_float4(0.f, 0.f, 0.f, 0.f);
    #pragma unroll 4
    for (int e = start; e < end; e++) {
        int2 rec = __ldg(&ge[e]);                 // uniform across warp -> broadcast
        float val = __int_as_float(rec.y);
        uint2 xw = Xv[(size_t)rec.x * 32 + lane];
        float2 fa = __half22float2(*(const half2*)&xw.x);
        float2 fb = __half22float2(*(const half2*)&xw.y);
        acc.x = fmaf(val, fa.x, acc.x);
        acc.y = fmaf(val, fa.y, acc.y);
        acc.z = fmaf(val, fb.x, acc.z);
        acc.w = fmaf(val, fb.y, acc.w);
    }
    ((float4*)outp)[(r * LL + l) * 32 + lane] = acc;   // [n][l][c]
}

// ----------------------------------------------------------------------------
// launch
// ----------------------------------------------------------------------------
extern "C" void kernel_launch(void* const* d_in, const int* in_sizes, int n_in,
                              void* d_out, int out_size) {
    const int*   phi_idx = (const int*)d_in[0];    // [L,2,E]
    const float* phi_val = (const float*)d_in[1];  // [L,E]
    const int*   inv_idx = (const int*)d_in[2];    // [L,2,E]
    const float* inv_val = (const float*)d_in[3];  // [L,E]
    const float* feats   = (const float*)d_in[4];  // [N,L,C]
    const float* W       = (const float*)d_in[5];  // [C,C]
    const float* theta   = (const float*)d_in[6];  // [N]
    float*       outp    = (float*)d_out;          // [N,L,C]

    zero_cnt_kernel<<<(NM * NN + 255) / 256, 256>>>();
    dim3 gE(EE / 512, NM);
    hist_kernel<<<gE, 128>>>(phi_idx, inv_idx);
    scan_kernel<<<NM, 1024>>>();
    scatter_kernel<<<gE, 128>>>(phi_idx, phi_val, inv_idx, inv_val);
    gemm_kernel<<<(LL * NN) / GEMM_R, 128>>>(feats, W);
    spmm_inv_kernel<<<(LL * NN) / 8, 256>>>(theta);
    spmm_phi_kernel<<<(LL * NN) / 8, 256>>>(outp);
}